// round 4
// baseline (speedup 1.0000x reference)
#include <cuda_runtime.h>
#include <cuda_bf16.h>

#define N_NODES 50000
#define N_EDGES 800000
#define D 64
#define BN_EPS 1e-5f

#define SCAN_BS 1024
#define NB1 ((N_NODES + SCAN_BS - 1) / SCAN_BS)   // 49

// Scratch (device globals; no allocations allowed).
__device__ float4 g_t[N_NODES * (D/4)];    // t' = (h@W) * dinv[node]
__device__ float4 g_h[N_NODES * (D/4)];    // layer output
__device__ float  g_dinv[N_NODES];
__device__ int    g_cnt[N_NODES];
__device__ int    g_off[N_NODES + 1];
__device__ int    g_fill[N_NODES];
__device__ int    g_blk[NB1];
__device__ int    g_csr[N_EDGES];

// ---------------------------------------------------------------------------
// Degree / dinv / CSR build
// ---------------------------------------------------------------------------
__global__ void hist_init_kernel() {
    int i = blockIdx.x * blockDim.x + threadIdx.x;
    if (i < N_NODES) g_cnt[i] = 0;
}

__global__ void hist_kernel(const int* __restrict__ coli) {
    int e = blockIdx.x * blockDim.x + threadIdx.x;
    if (e < N_EDGES) atomicAdd(&g_cnt[coli[e]], 1);
}

__global__ void dinv_kernel() {
    int i = blockIdx.x * blockDim.x + threadIdx.x;
    if (i < N_NODES) g_dinv[i] = rsqrtf((float)(g_cnt[i] + 1));  // +1 self loop
}

__global__ __launch_bounds__(256) void scan1_kernel() {
    __shared__ int sh[256];
    int tid = threadIdx.x;
    int base = blockIdx.x * SCAN_BS + tid * 4;
    int c[4];
    #pragma unroll
    for (int i = 0; i < 4; i++)
        c[i] = (base + i < N_NODES) ? g_cnt[base + i] : 0;
    int tot = c[0] + c[1] + c[2] + c[3];
    sh[tid] = tot;
    __syncthreads();
    #pragma unroll
    for (int o = 1; o < 256; o <<= 1) {
        int v = (tid >= o) ? sh[tid - o] : 0;
        __syncthreads();
        sh[tid] += v;
        __syncthreads();
    }
    int incl = sh[tid];
    int run = incl - tot;
    if (tid == 255) g_blk[blockIdx.x] = incl;
    #pragma unroll
    for (int i = 0; i < 4; i++) {
        if (base + i < N_NODES) g_off[base + i] = run;
        run += c[i];
    }
}

__global__ __launch_bounds__(256) void scan2_kernel() {
    __shared__ int sh[256];
    int tid = threadIdx.x;
    int v = (tid < NB1) ? g_blk[tid] : 0;
    sh[tid] = v;
    __syncthreads();
    #pragma unroll
    for (int o = 1; o < 256; o <<= 1) {
        int u = (tid >= o) ? sh[tid - o] : 0;
        __syncthreads();
        sh[tid] += u;
        __syncthreads();
    }
    if (tid < NB1) g_blk[tid] = sh[tid] - v;
}

__global__ void scan3_kernel() {
    int i = blockIdx.x * blockDim.x + threadIdx.x;
    if (i < N_NODES) {
        int off = g_off[i] + g_blk[i >> 10];
        g_off[i] = off;
        g_fill[i] = off;
        if (i == 0) g_off[N_NODES] = N_EDGES;
    }
}

__global__ void fill_kernel(const int* __restrict__ rowi,
                            const int* __restrict__ coli) {
    int e = blockIdx.x * blockDim.x + threadIdx.x;
    if (e < N_EDGES) {
        int c = coli[e];
        int pos = atomicAdd(&g_fill[c], 1);
        g_csr[pos] = rowi[e];
    }
}

// ---------------------------------------------------------------------------
// GEMM: t' = (in @ W) * dinv. 256-node tile, 256 threads.
// Thread = (node quad ng, 16-feat group fg): 4 nodes x 16 feats, 64 acc regs.
// in == nullptr -> read previous layer output g_h.
// ---------------------------------------------------------------------------
#define XPAD 65   // scalar-x row stride: 4*65 % 32 = 4 -> conflict-free ng spread
#define GEMM_SMEM_BYTES (16384 + 256 * XPAD * 4)

__global__ __launch_bounds__(256) void gemm_kernel(const float* __restrict__ in,
                                                   const float* __restrict__ W) {
    extern __shared__ float smem[];
    float4* sW = (float4*)smem;            // 1024 float4 = 16 KB
    float*  sx = smem + 4096;              // 256 rows x XPAD floats

    int tid = threadIdx.x;
    int node0 = blockIdx.x * 256;

    const float4* W4 = (const float4*)W;
    #pragma unroll
    for (int i = 0; i < 4; i++) sW[tid + 256 * i] = W4[tid + 256 * i];

    // Load 256 input rows (4096 float4, 16 per thread), coalesced; scalar store.
    #pragma unroll
    for (int i = 0; i < 16; i++) {
        int g = tid + 256 * i;
        int r = g >> 4;
        int c4 = g & 15;
        int node = node0 + r;
        float4 v = make_float4(0.f, 0.f, 0.f, 0.f);
        if (node < N_NODES) {
            if (in) v = ((const float4*)in)[node * 16 + c4];
            else    v = g_h[node * 16 + c4];
        }
        float* dst = sx + r * XPAD + c4 * 4;
        dst[0] = v.x; dst[1] = v.y; dst[2] = v.z; dst[3] = v.w;
    }
    __syncthreads();

    int fg = tid & 3;     // 16-feat group (4 float4s)
    int ng = tid >> 2;    // node quad (0..63)

    float4 acc[4][4];
    #pragma unroll
    for (int i = 0; i < 4; i++)
        #pragma unroll
        for (int j = 0; j < 4; j++)
            acc[i][j] = make_float4(0.f, 0.f, 0.f, 0.f);

    #pragma unroll 2
    for (int k = 0; k < D; k++) {
        float4 w0 = sW[k * 16 + fg * 4 + 0];
        float4 w1 = sW[k * 16 + fg * 4 + 1];
        float4 w2 = sW[k * 16 + fg * 4 + 2];
        float4 w3 = sW[k * 16 + fg * 4 + 3];
        #pragma unroll
        for (int i = 0; i < 4; i++) {
            float xv = sx[(ng * 4 + i) * XPAD + k];
            acc[i][0].x += xv * w0.x; acc[i][0].y += xv * w0.y;
            acc[i][0].z += xv * w0.z; acc[i][0].w += xv * w0.w;
            acc[i][1].x += xv * w1.x; acc[i][1].y += xv * w1.y;
            acc[i][1].z += xv * w1.z; acc[i][1].w += xv * w1.w;
            acc[i][2].x += xv * w2.x; acc[i][2].y += xv * w2.y;
            acc[i][2].z += xv * w2.z; acc[i][2].w += xv * w2.w;
            acc[i][3].x += xv * w3.x; acc[i][3].y += xv * w3.y;
            acc[i][3].z += xv * w3.z; acc[i][3].w += xv * w3.w;
        }
    }

    #pragma unroll
    for (int i = 0; i < 4; i++) {
        int node = node0 + ng * 4 + i;
        if (node < N_NODES) {
            float dv = g_dinv[node];
            #pragma unroll
            for (int j = 0; j < 4; j++) {
                float4 a = acc[i][j];
                a.x *= dv; a.y *= dv; a.z *= dv; a.w *= dv;
                g_t[node * 16 + fg * 4 + j] = a;
            }
        }
    }
}

// ---------------------------------------------------------------------------
// Aggregate (pull-mode) + fused BN/ReLU (+ final linear head when last).
// ---------------------------------------------------------------------------
__global__ __launch_bounds__(256) void aggregate_kernel(
        const float* __restrict__ b,
        const float* __restrict__ gamma,
        const float* __restrict__ beta,
        const float* __restrict__ mean,
        const float* __restrict__ var,
        const float* __restrict__ lin_w,
        const float* __restrict__ lin_b,
        float* __restrict__ out,
        int last) {
    int t = blockIdx.x * blockDim.x + threadIdx.x;
    int node = t >> 4;
    int sub = t & 15;
    if (node >= N_NODES) return;

    int s = g_off[node];
    int e = g_off[node + 1];

    float4 acc = g_t[node * (D/4) + sub];   // self loop (already dinv-scaled)

    int j = s;
    for (; j + 4 <= e; j += 4) {
        int n0 = __ldg(&g_csr[j + 0]);
        int n1 = __ldg(&g_csr[j + 1]);
        int n2 = __ldg(&g_csr[j + 2]);
        int n3 = __ldg(&g_csr[j + 3]);
        float4 v0 = g_t[n0 * (D/4) + sub];
        float4 v1 = g_t[n1 * (D/4) + sub];
        float4 v2 = g_t[n2 * (D/4) + sub];
        float4 v3 = g_t[n3 * (D/4) + sub];
        v0.x += v1.x; v0.y += v1.y; v0.z += v1.z; v0.w += v1.w;
        v2.x += v3.x; v2.y += v3.y; v2.z += v3.z; v2.w += v3.w;
        acc.x += v0.x + v2.x;
        acc.y += v0.y + v2.y;
        acc.z += v0.z + v2.z;
        acc.w += v0.w + v2.w;
    }
    for (; j < e; j++) {
        int n = __ldg(&g_csr[j]);
        float4 v = g_t[n * (D/4) + sub];
        acc.x += v.x; acc.y += v.y; acc.z += v.z; acc.w += v.w;
    }

    float dv = g_dinv[node];
    float4 bb = ((const float4*)b)[sub];
    float4 gm = ((const float4*)gamma)[sub];
    float4 bt = ((const float4*)beta)[sub];
    float4 mn = ((const float4*)mean)[sub];
    float4 vr = ((const float4*)var)[sub];

    float4 h;
    h.x = fmaxf(0.f, (acc.x * dv + bb.x - mn.x) * rsqrtf(vr.x + BN_EPS) * gm.x + bt.x);
    h.y = fmaxf(0.f, (acc.y * dv + bb.y - mn.y) * rsqrtf(vr.y + BN_EPS) * gm.y + bt.y);
    h.z = fmaxf(0.f, (acc.z * dv + bb.z - mn.z) * rsqrtf(vr.z + BN_EPS) * gm.z + bt.z);
    h.w = fmaxf(0.f, (acc.w * dv + bb.w - mn.w) * rsqrtf(vr.w + BN_EPS) * gm.w + bt.w);

    if (!last) {
        g_h[node * (D/4) + sub] = h;
    } else {
        float4 w = ((const float4*)lin_w)[sub];
        float dot = h.x * w.x + h.y * w.y + h.z * w.z + h.w * w.w;
        #pragma unroll
        for (int o = 8; o; o >>= 1)
            dot += __shfl_down_sync(0xFFFFFFFFu, dot, o, 16);
        if (sub == 0) out[node] = dot + lin_b[0];
    }
}

// ---------------------------------------------------------------------------
extern "C" void kernel_launch(void* const* d_in, const int* in_sizes, int n_in,
                              void* d_out, int out_size) {
    const float* x        = (const float*)d_in[0];
    const int*   ei       = (const int*)  d_in[1];   // [2, E]
    const float* Ws       = (const float*)d_in[2];   // [3, 64, 64]
    const float* bs       = (const float*)d_in[3];
    const float* gammas   = (const float*)d_in[4];
    const float* betas    = (const float*)d_in[5];
    const float* means    = (const float*)d_in[6];
    const float* variances= (const float*)d_in[7];
    const float* lin_w    = (const float*)d_in[8];
    const float* lin_b    = (const float*)d_in[9];

    const int* rowi = ei;
    const int* coli = ei + N_EDGES;

    // One-time host infra (created on the uncaptured correctness call; reused
    // identically on every call — same launches, same work, deterministic).
    static cudaStream_t s_side = nullptr;
    static cudaEvent_t s_evA = nullptr, s_evB = nullptr;
    if (!s_side) {
        cudaStreamCreate(&s_side);
        cudaEventCreateWithFlags(&s_evA, cudaEventDisableTiming);
        cudaEventCreateWithFlags(&s_evB, cudaEventDisableTiming);
        cudaFuncSetAttribute(gemm_kernel,
                             cudaFuncAttributeMaxDynamicSharedMemorySize,
                             GEMM_SMEM_BYTES);
    }

    // Degree + dinv first (gemm0's only dependency).
    hist_init_kernel<<<(N_NODES + 255) / 256, 256>>>();
    hist_kernel<<<(N_EDGES + 255) / 256, 256>>>(coli);
    dinv_kernel<<<(N_NODES + 255) / 256, 256>>>();

    // Fork: CSR scan+fill on side stream, concurrent with layer-0 GEMM.
    cudaEventRecord(s_evA, 0);
    cudaStreamWaitEvent(s_side, s_evA, 0);
    scan1_kernel<<<NB1, 256, 0, s_side>>>();
    scan2_kernel<<<1, 256, 0, s_side>>>();
    scan3_kernel<<<(N_NODES + 255) / 256, 256, 0, s_side>>>();
    fill_kernel<<<(N_EDGES + 255) / 256, 256, 0, s_side>>>(rowi, coli);
    cudaEventRecord(s_evB, s_side);

    const int gemm_blocks = (N_NODES + 255) / 256;
    const int agg_blocks = (N_NODES * 16 + 255) / 256;

    gemm_kernel<<<gemm_blocks, 256, GEMM_SMEM_BYTES>>>(x, Ws);

    // Join: aggregate needs the CSR.
    cudaStreamWaitEvent(0, s_evB, 0);

    for (int l = 0; l < 3; l++) {
        if (l > 0)
            gemm_kernel<<<gemm_blocks, 256, GEMM_SMEM_BYTES>>>(nullptr, Ws + l * D * D);
        aggregate_kernel<<<agg_blocks, 256>>>(bs + l * D, gammas + l * D,
                                              betas + l * D, means + l * D,
                                              variances + l * D,
                                              lin_w, lin_b, (float*)d_out,
                                              (l == 2) ? 1 : 0);
    }
}

// round 5
// speedup vs baseline: 1.1768x; 1.1768x over previous
#include <cuda_runtime.h>
#include <cuda_bf16.h>

#define N_NODES 50000
#define N_EDGES 800000
#define D 64
#define BN_EPS 1e-5f

#define SCAN_BS 1024
#define NB1 ((N_NODES + SCAN_BS - 1) / SCAN_BS)   // 49

// Scratch (device globals; no allocations allowed).
// INVARIANT: g_cnt is all-zero at kernel_launch entry (zero-init at load;
// scan3_kernel re-zeroes it after use within every call).
__device__ float4 g_t[N_NODES * (D/4)];    // t' = (h@W) * dinv[node]
__device__ float4 g_h[N_NODES * (D/4)];    // layer output
__device__ float  g_dinv[N_NODES];
__device__ int    g_cnt[N_NODES];
__device__ int    g_off[N_NODES + 1];
__device__ int    g_fill[N_NODES];
__device__ int    g_blk[NB1];
__device__ int    g_csr[N_EDGES];

// ---------------------------------------------------------------------------
// CSR build: hist -> scan1 (block partials) -> scan3 (prefix+dinv+cursors) -> fill
// ---------------------------------------------------------------------------
__global__ void hist_kernel(const int* __restrict__ coli) {
    int e = blockIdx.x * blockDim.x + threadIdx.x;
    if (e < N_EDGES) atomicAdd(&g_cnt[coli[e]], 1);
}

__global__ __launch_bounds__(256) void scan1_kernel() {
    __shared__ int sh[256];
    int tid = threadIdx.x;
    int base = blockIdx.x * SCAN_BS + tid * 4;
    int c[4];
    #pragma unroll
    for (int i = 0; i < 4; i++)
        c[i] = (base + i < N_NODES) ? g_cnt[base + i] : 0;
    int tot = c[0] + c[1] + c[2] + c[3];
    sh[tid] = tot;
    __syncthreads();
    #pragma unroll
    for (int o = 1; o < 256; o <<= 1) {
        int v = (tid >= o) ? sh[tid - o] : 0;
        __syncthreads();
        sh[tid] += v;
        __syncthreads();
    }
    int incl = sh[tid];
    int run = incl - tot;
    if (tid == 255) g_blk[blockIdx.x] = incl;
    #pragma unroll
    for (int i = 0; i < 4; i++) {
        if (base + i < N_NODES) g_off[base + i] = run;
        run += c[i];
    }
}

// Per 256-node block: add prefix of scan1 partials, compute dinv, set fill
// cursors, and re-zero g_cnt (restores the entry invariant).
__global__ __launch_bounds__(256) void scan3_kernel() {
    __shared__ int pref;
    int tid = threadIdx.x;
    if (tid == 0) pref = 0;
    __syncthreads();
    // This block's 256 nodes lie inside one scan1 chunk of 1024 nodes.
    int chunk = (blockIdx.x * 256) >> 10;
    if (tid < chunk) atomicAdd(&pref, g_blk[tid]);   // chunk <= 48 < 256
    __syncthreads();

    int i = blockIdx.x * 256 + tid;
    if (i < N_NODES) {
        int cnt = g_cnt[i];
        int off = g_off[i] + pref;
        g_off[i] = off;
        g_fill[i] = off;
        g_dinv[i] = rsqrtf((float)(cnt + 1));   // +1 self loop
        g_cnt[i] = 0;                           // restore invariant
        if (i == 0) g_off[N_NODES] = N_EDGES;
    }
}

__global__ void fill_kernel(const int* __restrict__ rowi,
                            const int* __restrict__ coli) {
    int e = blockIdx.x * blockDim.x + threadIdx.x;
    if (e < N_EDGES) {
        int c = coli[e];
        int pos = atomicAdd(&g_fill[c], 1);
        g_csr[pos] = rowi[e];
    }
}

// ---------------------------------------------------------------------------
// GEMM: t' = (in @ W) * dinv.  64-node tile, 256 threads.
// Thread = (node quad nq, feature group jg): 4 nodes x 4 feats.
// Inner loop vectorized over k by 4 (float4 x loads).
// in == nullptr -> read previous layer output g_h.
// ---------------------------------------------------------------------------
#define XPAD 68            // floats per padded row; 17 float4s

__global__ __launch_bounds__(256) void gemm_kernel(const float* __restrict__ in,
                                                   const float* __restrict__ W) {
    __shared__ float4 sW[D * (D/4)];      // 16 KB
    __shared__ float4 sx4[64 * (XPAD/4)]; // 64 rows x 17 float4 = ~17 KB

    int tid = threadIdx.x;
    int node0 = blockIdx.x * 64;

    const float4* W4 = (const float4*)W;
    #pragma unroll
    for (int i = 0; i < 4; i++) sW[tid + 256 * i] = W4[tid + 256 * i];

    #pragma unroll
    for (int i = 0; i < 4; i++) {
        int g = tid + 256 * i;
        int r = g >> 4;
        int c4 = g & 15;
        int node = node0 + r;
        float4 v = make_float4(0.f, 0.f, 0.f, 0.f);
        if (node < N_NODES) {
            if (in) v = ((const float4*)in)[node * (D/4) + c4];
            else    v = g_h[node * (D/4) + c4];
        }
        sx4[r * (XPAD/4) + c4] = v;
    }
    __syncthreads();

    int jg = tid & 15;     // output feature group
    int nq = tid >> 4;     // node quad (0..15)

    float4 acc[4];
    #pragma unroll
    for (int i = 0; i < 4; i++) acc[i] = make_float4(0.f, 0.f, 0.f, 0.f);

    #pragma unroll 4
    for (int k4 = 0; k4 < 16; k4++) {
        float4 w0 = sW[(4 * k4 + 0) * 16 + jg];
        float4 w1 = sW[(4 * k4 + 1) * 16 + jg];
        float4 w2 = sW[(4 * k4 + 2) * 16 + jg];
        float4 w3 = sW[(4 * k4 + 3) * 16 + jg];
        #pragma unroll
        for (int i = 0; i < 4; i++) {
            float4 xv = sx4[(nq * 4 + i) * (XPAD/4) + k4];
            acc[i].x += xv.x * w0.x; acc[i].y += xv.x * w0.y;
            acc[i].z += xv.x * w0.z; acc[i].w += xv.x * w0.w;
            acc[i].x += xv.y * w1.x; acc[i].y += xv.y * w1.y;
            acc[i].z += xv.y * w1.z; acc[i].w += xv.y * w1.w;
            acc[i].x += xv.z * w2.x; acc[i].y += xv.z * w2.y;
            acc[i].z += xv.z * w2.z; acc[i].w += xv.z * w2.w;
            acc[i].x += xv.w * w3.x; acc[i].y += xv.w * w3.y;
            acc[i].z += xv.w * w3.z; acc[i].w += xv.w * w3.w;
        }
    }

    #pragma unroll
    for (int i = 0; i < 4; i++) {
        int node = node0 + nq * 4 + i;
        if (node < N_NODES) {
            float dv = g_dinv[node];
            float4 a = acc[i];
            a.x *= dv; a.y *= dv; a.z *= dv; a.w *= dv;
            g_t[node * (D/4) + jg] = a;
        }
    }
}

// ---------------------------------------------------------------------------
// Aggregate (pull-mode) + fused BN/ReLU (+ final linear head when last).
// 16 threads per node (one float4 lane each).
// ---------------------------------------------------------------------------
__global__ __launch_bounds__(256) void aggregate_kernel(
        const float* __restrict__ b,
        const float* __restrict__ gamma,
        const float* __restrict__ beta,
        const float* __restrict__ mean,
        const float* __restrict__ var,
        const float* __restrict__ lin_w,
        const float* __restrict__ lin_b,
        float* __restrict__ out,
        int last) {
    int t = blockIdx.x * blockDim.x + threadIdx.x;
    int node = t >> 4;
    int sub = t & 15;
    if (node >= N_NODES) return;

    int s = g_off[node];
    int e = g_off[node + 1];

    float4 acc = g_t[node * (D/4) + sub];   // self loop (already dinv-scaled)

    int j = s;
    for (; j + 4 <= e; j += 4) {
        int n0 = __ldg(&g_csr[j + 0]);
        int n1 = __ldg(&g_csr[j + 1]);
        int n2 = __ldg(&g_csr[j + 2]);
        int n3 = __ldg(&g_csr[j + 3]);
        float4 v0 = g_t[n0 * (D/4) + sub];
        float4 v1 = g_t[n1 * (D/4) + sub];
        float4 v2 = g_t[n2 * (D/4) + sub];
        float4 v3 = g_t[n3 * (D/4) + sub];
        v0.x += v1.x; v0.y += v1.y; v0.z += v1.z; v0.w += v1.w;
        v2.x += v3.x; v2.y += v3.y; v2.z += v3.z; v2.w += v3.w;
        acc.x += v0.x + v2.x;
        acc.y += v0.y + v2.y;
        acc.z += v0.z + v2.z;
        acc.w += v0.w + v2.w;
    }
    for (; j < e; j++) {
        int n = __ldg(&g_csr[j]);
        float4 v = g_t[n * (D/4) + sub];
        acc.x += v.x; acc.y += v.y; acc.z += v.z; acc.w += v.w;
    }

    float dv = g_dinv[node];
    float4 bb = ((const float4*)b)[sub];
    float4 gm = ((const float4*)gamma)[sub];
    float4 bt = ((const float4*)beta)[sub];
    float4 mn = ((const float4*)mean)[sub];
    float4 vr = ((const float4*)var)[sub];

    float4 h;
    h.x = fmaxf(0.f, (acc.x * dv + bb.x - mn.x) * rsqrtf(vr.x + BN_EPS) * gm.x + bt.x);
    h.y = fmaxf(0.f, (acc.y * dv + bb.y - mn.y) * rsqrtf(vr.y + BN_EPS) * gm.y + bt.y);
    h.z = fmaxf(0.f, (acc.z * dv + bb.z - mn.z) * rsqrtf(vr.z + BN_EPS) * gm.z + bt.z);
    h.w = fmaxf(0.f, (acc.w * dv + bb.w - mn.w) * rsqrtf(vr.w + BN_EPS) * gm.w + bt.w);

    if (!last) {
        g_h[node * (D/4) + sub] = h;
    } else {
        float4 w = ((const float4*)lin_w)[sub];
        float dot = h.x * w.x + h.y * w.y + h.z * w.z + h.w * w.w;
        #pragma unroll
        for (int o = 8; o; o >>= 1)
            dot += __shfl_down_sync(0xFFFFFFFFu, dot, o, 16);
        if (sub == 0) out[node] = dot + lin_b[0];
    }
}

// ---------------------------------------------------------------------------
extern "C" void kernel_launch(void* const* d_in, const int* in_sizes, int n_in,
                              void* d_out, int out_size) {
    const float* x        = (const float*)d_in[0];
    const int*   ei       = (const int*)  d_in[1];   // [2, E]
    const float* Ws       = (const float*)d_in[2];   // [3, 64, 64]
    const float* bs       = (const float*)d_in[3];
    const float* gammas   = (const float*)d_in[4];
    const float* betas    = (const float*)d_in[5];
    const float* means    = (const float*)d_in[6];
    const float* variances= (const float*)d_in[7];
    const float* lin_w    = (const float*)d_in[8];
    const float* lin_b    = (const float*)d_in[9];

    const int* rowi = ei;
    const int* coli = ei + N_EDGES;

    // CSR build (4 launches; g_cnt zero-on-entry invariant removes hist_init,
    // scan3's inline partial-prefix removes scan2)
    hist_kernel<<<(N_EDGES + 255) / 256, 256>>>(coli);
    scan1_kernel<<<NB1, 256>>>();
    scan3_kernel<<<(N_NODES + 255) / 256, 256>>>();
    fill_kernel<<<(N_EDGES + 255) / 256, 256>>>(rowi, coli);

    const int gemm_blocks = (N_NODES + 63) / 64;
    const int agg_blocks = (N_NODES * 16 + 255) / 256;

    for (int l = 0; l < 3; l++) {
        const float* in = (l == 0) ? x : nullptr;   // nullptr -> g_h
        gemm_kernel<<<gemm_blocks, 256>>>(in, Ws + l * D * D);
        aggregate_kernel<<<agg_blocks, 256>>>(bs + l * D, gammas + l * D,
                                              betas + l * D, means + l * D,
                                              variances + l * D,
                                              lin_w, lin_b, (float*)d_out,
                                              (l == 2) ? 1 : 0);
    }
}

// round 6
// speedup vs baseline: 1.3085x; 1.1119x over previous
#include <cuda_runtime.h>
#include <cuda_fp16.h>
#include <cuda_bf16.h>

#define N_NODES 50000
#define N_EDGES 800000
#define D 64
#define BN_EPS 1e-5f

#define SCAN_BS 1024
#define NB1 ((N_NODES + SCAN_BS - 1) / SCAN_BS)   // 49

// Scratch (device globals; no allocations allowed).
// INVARIANT: g_cnt is all-zero at kernel_launch entry (zero-init at load;
// scan3_kernel re-zeroes it after use within every call).
__device__ uint2  g_t16[N_NODES * 16];     // t' = (h@W)*dinv, fp16 (row = 64 halves)
__device__ float4 g_h[N_NODES * (D/4)];    // layer output (fp32)
__device__ float  g_dinv[N_NODES];
__device__ int    g_cnt[N_NODES];
__device__ int    g_off[N_NODES + 1];
__device__ int    g_fill[N_NODES];
__device__ int    g_blk[NB1];
__device__ int    g_csr[N_EDGES];

__device__ __forceinline__ float2 h2_to_f2(unsigned u) {
    __half2 h = *reinterpret_cast<__half2*>(&u);
    return __half22float2(h);
}

// ---------------------------------------------------------------------------
// CSR build: hist -> scan1 -> scan3 -> fill
// ---------------------------------------------------------------------------
__global__ void hist_kernel(const int* __restrict__ coli) {
    int idx = blockIdx.x * blockDim.x + threadIdx.x;   // int4 index
    if (idx < N_EDGES / 4) {
        int4 c = ((const int4*)coli)[idx];
        atomicAdd(&g_cnt[c.x], 1);
        atomicAdd(&g_cnt[c.y], 1);
        atomicAdd(&g_cnt[c.z], 1);
        atomicAdd(&g_cnt[c.w], 1);
    }
}

__global__ __launch_bounds__(256) void scan1_kernel() {
    __shared__ int sh[8];
    int tid = threadIdx.x;
    int lane = tid & 31;
    int wid = tid >> 5;
    int base = blockIdx.x * SCAN_BS + tid * 4;

    int c[4];
    #pragma unroll
    for (int i = 0; i < 4; i++)
        c[i] = (base + i < N_NODES) ? g_cnt[base + i] : 0;
    int tot = c[0] + c[1] + c[2] + c[3];

    // warp-inclusive scan of tot
    int v = tot;
    #pragma unroll
    for (int o = 1; o < 32; o <<= 1) {
        int n = __shfl_up_sync(0xFFFFFFFFu, v, o);
        if (lane >= o) v += n;
    }
    if (lane == 31) sh[wid] = v;
    __syncthreads();
    if (tid < 8) {
        int w = sh[tid];
        #pragma unroll
        for (int o = 1; o < 8; o <<= 1) {
            int n = __shfl_up_sync(0xFFu, w, o, 8);
            if (tid >= o) w += n;
        }
        sh[tid] = w;   // inclusive warp prefix
    }
    __syncthreads();
    int incl = v + ((wid > 0) ? sh[wid - 1] : 0);
    int run = incl - tot;
    if (tid == 255) g_blk[blockIdx.x] = incl;
    #pragma unroll
    for (int i = 0; i < 4; i++) {
        if (base + i < N_NODES) g_off[base + i] = run;
        run += c[i];
    }
}

// Per 256-node block: add prefix of scan1 partials, dinv, fill cursors,
// re-zero g_cnt (restores entry invariant).
__global__ __launch_bounds__(256) void scan3_kernel() {
    __shared__ int pref;
    int tid = threadIdx.x;
    if (tid == 0) pref = 0;
    __syncthreads();
    int chunk = (blockIdx.x * 256) >> 10;
    if (tid < chunk) atomicAdd(&pref, g_blk[tid]);   // chunk <= 48 < 256
    __syncthreads();

    int i = blockIdx.x * 256 + tid;
    if (i < N_NODES) {
        int cnt = g_cnt[i];
        int off = g_off[i] + pref;
        g_off[i] = off;
        g_fill[i] = off;
        g_dinv[i] = rsqrtf((float)(cnt + 1));   // +1 self loop
        g_cnt[i] = 0;                           // restore invariant
        if (i == 0) g_off[N_NODES] = N_EDGES;
    }
}

__global__ void fill_kernel(const int* __restrict__ rowi,
                            const int* __restrict__ coli) {
    int idx = blockIdx.x * blockDim.x + threadIdx.x;   // int4 index
    if (idx < N_EDGES / 4) {
        int4 r = ((const int4*)rowi)[idx];
        int4 c = ((const int4*)coli)[idx];
        int p0 = atomicAdd(&g_fill[c.x], 1);
        int p1 = atomicAdd(&g_fill[c.y], 1);
        int p2 = atomicAdd(&g_fill[c.z], 1);
        int p3 = atomicAdd(&g_fill[c.w], 1);
        g_csr[p0] = r.x;
        g_csr[p1] = r.y;
        g_csr[p2] = r.z;
        g_csr[p3] = r.w;
    }
}

// ---------------------------------------------------------------------------
// GEMM: t' = (in @ W) * dinv, stored fp16.  64-node tile, 256 threads.
// Thread = (node quad nq, feature group jg): 4 nodes x 4 feats.
// in == nullptr -> read previous layer output g_h.
// ---------------------------------------------------------------------------
#define XPAD 68            // floats per padded row; 17 float4s

__global__ __launch_bounds__(256) void gemm_kernel(const float* __restrict__ in,
                                                   const float* __restrict__ W) {
    __shared__ float4 sW[D * (D/4)];      // 16 KB
    __shared__ float4 sx4[64 * (XPAD/4)];

    int tid = threadIdx.x;
    int node0 = blockIdx.x * 64;

    const float4* W4 = (const float4*)W;
    #pragma unroll
    for (int i = 0; i < 4; i++) sW[tid + 256 * i] = W4[tid + 256 * i];

    #pragma unroll
    for (int i = 0; i < 4; i++) {
        int g = tid + 256 * i;
        int r = g >> 4;
        int c4 = g & 15;
        int node = node0 + r;
        float4 v = make_float4(0.f, 0.f, 0.f, 0.f);
        if (node < N_NODES) {
            if (in) v = ((const float4*)in)[node * (D/4) + c4];
            else    v = g_h[node * (D/4) + c4];
        }
        sx4[r * (XPAD/4) + c4] = v;
    }
    __syncthreads();

    int jg = tid & 15;     // output feature group
    int nq = tid >> 4;     // node quad (0..15)

    float4 acc[4];
    #pragma unroll
    for (int i = 0; i < 4; i++) acc[i] = make_float4(0.f, 0.f, 0.f, 0.f);

    #pragma unroll 4
    for (int k4 = 0; k4 < 16; k4++) {
        float4 w0 = sW[(4 * k4 + 0) * 16 + jg];
        float4 w1 = sW[(4 * k4 + 1) * 16 + jg];
        float4 w2 = sW[(4 * k4 + 2) * 16 + jg];
        float4 w3 = sW[(4 * k4 + 3) * 16 + jg];
        #pragma unroll
        for (int i = 0; i < 4; i++) {
            float4 xv = sx4[(nq * 4 + i) * (XPAD/4) + k4];
            acc[i].x += xv.x * w0.x; acc[i].y += xv.x * w0.y;
            acc[i].z += xv.x * w0.z; acc[i].w += xv.x * w0.w;
            acc[i].x += xv.y * w1.x; acc[i].y += xv.y * w1.y;
            acc[i].z += xv.y * w1.z; acc[i].w += xv.y * w1.w;
            acc[i].x += xv.z * w2.x; acc[i].y += xv.z * w2.y;
            acc[i].z += xv.z * w2.z; acc[i].w += xv.z * w2.w;
            acc[i].x += xv.w * w3.x; acc[i].y += xv.w * w3.y;
            acc[i].z += xv.w * w3.z; acc[i].w += xv.w * w3.w;
        }
    }

    #pragma unroll
    for (int i = 0; i < 4; i++) {
        int node = node0 + nq * 4 + i;
        if (node < N_NODES) {
            float dv = g_dinv[node];
            float4 a = acc[i];
            a.x *= dv; a.y *= dv; a.z *= dv; a.w *= dv;
            __half2 lo = __floats2half2_rn(a.x, a.y);
            __half2 hi = __floats2half2_rn(a.z, a.w);
            uint2 p;
            p.x = *reinterpret_cast<unsigned*>(&lo);
            p.y = *reinterpret_cast<unsigned*>(&hi);
            g_t16[node * 16 + jg] = p;
        }
    }
}

// ---------------------------------------------------------------------------
// Aggregate (pull-mode, fp16 gather, fp32 accumulate) + fused BN/ReLU
// (+ final linear head when last).  8 threads per node, 8 feats each (16B).
// ---------------------------------------------------------------------------
__global__ __launch_bounds__(256) void aggregate_kernel(
        const float* __restrict__ b,
        const float* __restrict__ gamma,
        const float* __restrict__ beta,
        const float* __restrict__ mean,
        const float* __restrict__ var,
        const float* __restrict__ lin_w,
        const float* __restrict__ lin_b,
        float* __restrict__ out,
        int last) {
    int t = blockIdx.x * blockDim.x + threadIdx.x;
    int node = t >> 3;
    int sub = t & 7;        // 8-feat group
    if (node >= N_NODES) return;

    const uint4* T = (const uint4*)g_t16;   // row = 8 uint4

    int s = g_off[node];
    int e = g_off[node + 1];

    // self loop (already dinv-scaled)
    float2 a0, a1, a2, a3;
    {
        uint4 v = T[node * 8 + sub];
        a0 = h2_to_f2(v.x); a1 = h2_to_f2(v.y);
        a2 = h2_to_f2(v.z); a3 = h2_to_f2(v.w);
    }

    int j = s;
    for (; j + 4 <= e; j += 4) {
        int n0 = __ldg(&g_csr[j + 0]);
        int n1 = __ldg(&g_csr[j + 1]);
        int n2 = __ldg(&g_csr[j + 2]);
        int n3 = __ldg(&g_csr[j + 3]);
        uint4 v0 = T[n0 * 8 + sub];
        uint4 v1 = T[n1 * 8 + sub];
        uint4 v2 = T[n2 * 8 + sub];
        uint4 v3 = T[n3 * 8 + sub];
        float2 f;
        f = h2_to_f2(v0.x); a0.x += f.x; a0.y += f.y;
        f = h2_to_f2(v0.y); a1.x += f.x; a1.y += f.y;
        f = h2_to_f2(v0.z); a2.x += f.x; a2.y += f.y;
        f = h2_to_f2(v0.w); a3.x += f.x; a3.y += f.y;
        f = h2_to_f2(v1.x); a0.x += f.x; a0.y += f.y;
        f = h2_to_f2(v1.y); a1.x += f.x; a1.y += f.y;
        f = h2_to_f2(v1.z); a2.x += f.x; a2.y += f.y;
        f = h2_to_f2(v1.w); a3.x += f.x; a3.y += f.y;
        f = h2_to_f2(v2.x); a0.x += f.x; a0.y += f.y;
        f = h2_to_f2(v2.y); a1.x += f.x; a1.y += f.y;
        f = h2_to_f2(v2.z); a2.x += f.x; a2.y += f.y;
        f = h2_to_f2(v2.w); a3.x += f.x; a3.y += f.y;
        f = h2_to_f2(v3.x); a0.x += f.x; a0.y += f.y;
        f = h2_to_f2(v3.y); a1.x += f.x; a1.y += f.y;
        f = h2_to_f2(v3.z); a2.x += f.x; a2.y += f.y;
        f = h2_to_f2(v3.w); a3.x += f.x; a3.y += f.y;
    }
    for (; j < e; j++) {
        int n = __ldg(&g_csr[j]);
        uint4 v = T[n * 8 + sub];
        float2 f;
        f = h2_to_f2(v.x); a0.x += f.x; a0.y += f.y;
        f = h2_to_f2(v.y); a1.x += f.x; a1.y += f.y;
        f = h2_to_f2(v.z); a2.x += f.x; a2.y += f.y;
        f = h2_to_f2(v.w); a3.x += f.x; a3.y += f.y;
    }

    float dv = g_dinv[node];
    float4 acc0 = make_float4(a0.x, a0.y, a1.x, a1.y);
    float4 acc1 = make_float4(a2.x, a2.y, a3.x, a3.y);

    float4 h0, h1;
    {
        float4 bb = ((const float4*)b)[sub * 2 + 0];
        float4 gm = ((const float4*)gamma)[sub * 2 + 0];
        float4 bt = ((const float4*)beta)[sub * 2 + 0];
        float4 mn = ((const float4*)mean)[sub * 2 + 0];
        float4 vr = ((const float4*)var)[sub * 2 + 0];
        h0.x = fmaxf(0.f, (acc0.x * dv + bb.x - mn.x) * rsqrtf(vr.x + BN_EPS) * gm.x + bt.x);
        h0.y = fmaxf(0.f, (acc0.y * dv + bb.y - mn.y) * rsqrtf(vr.y + BN_EPS) * gm.y + bt.y);
        h0.z = fmaxf(0.f, (acc0.z * dv + bb.z - mn.z) * rsqrtf(vr.z + BN_EPS) * gm.z + bt.z);
        h0.w = fmaxf(0.f, (acc0.w * dv + bb.w - mn.w) * rsqrtf(vr.w + BN_EPS) * gm.w + bt.w);
    }
    {
        float4 bb = ((const float4*)b)[sub * 2 + 1];
        float4 gm = ((const float4*)gamma)[sub * 2 + 1];
        float4 bt = ((const float4*)beta)[sub * 2 + 1];
        float4 mn = ((const float4*)mean)[sub * 2 + 1];
        float4 vr = ((const float4*)var)[sub * 2 + 1];
        h1.x = fmaxf(0.f, (acc1.x * dv + bb.x - mn.x) * rsqrtf(vr.x + BN_EPS) * gm.x + bt.x);
        h1.y = fmaxf(0.f, (acc1.y * dv + bb.y - mn.y) * rsqrtf(vr.y + BN_EPS) * gm.y + bt.y);
        h1.z = fmaxf(0.f, (acc1.z * dv + bb.z - mn.z) * rsqrtf(vr.z + BN_EPS) * gm.z + bt.z);
        h1.w = fmaxf(0.f, (acc1.w * dv + bb.w - mn.w) * rsqrtf(vr.w + BN_EPS) * gm.w + bt.w);
    }

    if (!last) {
        ((float4*)g_h)[node * 16 + sub * 2 + 0] = h0;
        ((float4*)g_h)[node * 16 + sub * 2 + 1] = h1;
    } else {
        float4 w0 = ((const float4*)lin_w)[sub * 2 + 0];
        float4 w1 = ((const float4*)lin_w)[sub * 2 + 1];
        float dot = h0.x * w0.x + h0.y * w0.y + h0.z * w0.z + h0.w * w0.w
                  + h1.x * w1.x + h1.y * w1.y + h1.z * w1.z + h1.w * w1.w;
        #pragma unroll
        for (int o = 4; o; o >>= 1)
            dot += __shfl_down_sync(0xFFFFFFFFu, dot, o, 8);
        if (sub == 0) out[node] = dot + lin_b[0];
    }
}

// ---------------------------------------------------------------------------
extern "C" void kernel_launch(void* const* d_in, const int* in_sizes, int n_in,
                              void* d_out, int out_size) {
    const float* x        = (const float*)d_in[0];
    const int*   ei       = (const int*)  d_in[1];   // [2, E]
    const float* Ws       = (const float*)d_in[2];   // [3, 64, 64]
    const float* bs       = (const float*)d_in[3];
    const float* gammas   = (const float*)d_in[4];
    const float* betas    = (const float*)d_in[5];
    const float* means    = (const float*)d_in[6];
    const float* variances= (const float*)d_in[7];
    const float* lin_w    = (const float*)d_in[8];
    const float* lin_b    = (const float*)d_in[9];

    const int* rowi = ei;
    const int* coli = ei + N_EDGES;

    const int e4_blocks = (N_EDGES / 4 + 255) / 256;
    hist_kernel<<<e4_blocks, 256>>>(coli);
    scan1_kernel<<<NB1, 256>>>();
    scan3_kernel<<<(N_NODES + 255) / 256, 256>>>();
    fill_kernel<<<e4_blocks, 256>>>(rowi, coli);

    const int gemm_blocks = (N_NODES + 63) / 64;
    const int agg_blocks = (N_NODES * 8 + 255) / 256;

    for (int l = 0; l < 3; l++) {
        const float* in = (l == 0) ? x : nullptr;   // nullptr -> g_h
        gemm_kernel<<<gemm_blocks, 256>>>(in, Ws + l * D * D);
        aggregate_kernel<<<agg_blocks, 256>>>(bs + l * D, gammas + l * D,
                                              betas + l * D, means + l * D,
                                              variances + l * D,
                                              lin_w, lin_b, (float*)d_out,
                                              (l == 2) ? 1 : 0);
    }
}

// round 7
// speedup vs baseline: 1.5942x; 1.2184x over previous
#include <cuda_runtime.h>
#include <cuda_fp16.h>
#include <cuda_bf16.h>

#define N_NODES 50000
#define N_EDGES 800000
#define D 64
#define BN_EPS 1e-5f

#define SCAN_BS 1024
#define NB1 ((N_NODES + SCAN_BS - 1) / SCAN_BS)   // 49

// Scratch (device globals; no allocations allowed).
// INVARIANT: g_cnt is all-zero at kernel_launch entry (zero-init at load;
// scan3_kernel re-zeroes it after use within every call).
__device__ uint2  g_t16[N_NODES * 16];     // t' = (h@W)*dinv, fp16 (row = 64 halves)
__device__ float4 g_h[N_NODES * (D/4)];    // layer output (fp32)
__device__ float  g_dinv[N_NODES];
__device__ int    g_cnt[N_NODES];
__device__ int    g_off[N_NODES + 1];
__device__ int    g_fill[N_NODES];
__device__ int    g_blk[NB1];
__device__ int    g_csr[N_EDGES];

__device__ __forceinline__ float2 h2_to_f2(unsigned u) {
    __half2 h = *reinterpret_cast<__half2*>(&u);
    return __half22float2(h);
}

__device__ __forceinline__ unsigned smem_u32(const void* p) {
    return (unsigned)__cvta_generic_to_shared(p);
}

// ---------------------------------------------------------------------------
// CSR build: hist -> scan1 -> scan3 -> fill
// ---------------------------------------------------------------------------
__global__ void hist_kernel(const int* __restrict__ coli) {
    int idx = blockIdx.x * blockDim.x + threadIdx.x;   // int4 index
    if (idx < N_EDGES / 4) {
        int4 c = ((const int4*)coli)[idx];
        atomicAdd(&g_cnt[c.x], 1);
        atomicAdd(&g_cnt[c.y], 1);
        atomicAdd(&g_cnt[c.z], 1);
        atomicAdd(&g_cnt[c.w], 1);
    }
}

__global__ __launch_bounds__(256) void scan1_kernel() {
    __shared__ int sh[8];
    int tid = threadIdx.x;
    int lane = tid & 31;
    int wid = tid >> 5;
    int base = blockIdx.x * SCAN_BS + tid * 4;

    int c[4];
    #pragma unroll
    for (int i = 0; i < 4; i++)
        c[i] = (base + i < N_NODES) ? g_cnt[base + i] : 0;
    int tot = c[0] + c[1] + c[2] + c[3];

    int v = tot;
    #pragma unroll
    for (int o = 1; o < 32; o <<= 1) {
        int n = __shfl_up_sync(0xFFFFFFFFu, v, o);
        if (lane >= o) v += n;
    }
    if (lane == 31) sh[wid] = v;
    __syncthreads();
    if (tid < 8) {
        int w = sh[tid];
        #pragma unroll
        for (int o = 1; o < 8; o <<= 1) {
            int n = __shfl_up_sync(0xFFu, w, o, 8);
            if (tid >= o) w += n;
        }
        sh[tid] = w;
    }
    __syncthreads();
    int incl = v + ((wid > 0) ? sh[wid - 1] : 0);
    int run = incl - tot;
    if (tid == 255) g_blk[blockIdx.x] = incl;
    #pragma unroll
    for (int i = 0; i < 4; i++) {
        if (base + i < N_NODES) g_off[base + i] = run;
        run += c[i];
    }
}

__global__ __launch_bounds__(256) void scan3_kernel() {
    __shared__ int pref;
    int tid = threadIdx.x;
    if (tid == 0) pref = 0;
    __syncthreads();
    int chunk = (blockIdx.x * 256) >> 10;
    if (tid < chunk) atomicAdd(&pref, g_blk[tid]);   // chunk <= 48 < 256
    __syncthreads();

    int i = blockIdx.x * 256 + tid;
    if (i < N_NODES) {
        int cnt = g_cnt[i];
        int off = g_off[i] + pref;
        g_off[i] = off;
        g_fill[i] = off;
        g_dinv[i] = rsqrtf((float)(cnt + 1));   // +1 self loop
        g_cnt[i] = 0;                           // restore invariant
        if (i == 0) g_off[N_NODES] = N_EDGES;
    }
}

__global__ void fill_kernel(const int* __restrict__ rowi,
                            const int* __restrict__ coli) {
    int idx = blockIdx.x * blockDim.x + threadIdx.x;   // int4 index
    if (idx < N_EDGES / 4) {
        int4 r = ((const int4*)rowi)[idx];
        int4 c = ((const int4*)coli)[idx];
        int p0 = atomicAdd(&g_fill[c.x], 1);
        int p1 = atomicAdd(&g_fill[c.y], 1);
        int p2 = atomicAdd(&g_fill[c.z], 1);
        int p3 = atomicAdd(&g_fill[c.w], 1);
        g_csr[p0] = r.x;
        g_csr[p1] = r.y;
        g_csr[p2] = r.z;
        g_csr[p3] = r.w;
    }
}

// ---------------------------------------------------------------------------
// GEMM via HMMA: t' = (in @ W) * dinv, fp16 in / fp32 accum / fp16 out.
// 128-node tile, 256 threads (8 warps); warp = 16 rows x 64 cols.
// mma.sync.m16n8k16: 4 k-chunks x 8 n-chunks per warp.
// in == nullptr -> read previous layer output g_h (fp32).
// ---------------------------------------------------------------------------
#define APAD 72   // halves per smem row (bank 4r%32 distinct over 8 rows)

__global__ __launch_bounds__(256) void gemm_kernel(const float* __restrict__ in,
                                                   const float* __restrict__ W) {
    __shared__ __half sA[128 * APAD];   // 18432 B
    __shared__ __half sB[64 * APAD];    // 9216 B  (W as [k][n], n contiguous)

    int tid = threadIdx.x;
    int node0 = blockIdx.x * 128;

    // Fill W -> fp16 smem [k][n] row-major (n contiguous), padded rows.
    #pragma unroll
    for (int i = 0; i < 8; i++) {
        int g = tid + 256 * i;          // 0..2047, float2 granularity
        int k = g >> 5;                 // 64 float2 per... (64 n / 2)
        int n2 = g & 31;
        float2 w = ((const float2*)W)[k * 32 + n2];
        *(__half2*)&sB[k * APAD + n2 * 2] = __floats2half2_rn(w.x, w.y);
    }

    // Fill A: 128 rows x 64 feats fp32 -> fp16, padded rows.
    #pragma unroll
    for (int i = 0; i < 8; i++) {
        int g = tid + 256 * i;          // 0..2047
        int r = g >> 4;
        int c4 = g & 15;
        int node = node0 + r;
        float4 v = make_float4(0.f, 0.f, 0.f, 0.f);
        if (node < N_NODES) {
            if (in) v = ((const float4*)in)[node * 16 + c4];
            else    v = ((const float4*)g_h)[node * 16 + c4];
        }
        __half2* dst = (__half2*)&sA[r * APAD + c4 * 4];
        dst[0] = __floats2half2_rn(v.x, v.y);
        dst[1] = __floats2half2_rn(v.z, v.w);
    }
    __syncthreads();

    int warp = tid >> 5;
    int lane = tid & 31;

    float acc[8][4];
    #pragma unroll
    for (int nc = 0; nc < 8; nc++)
        #pragma unroll
        for (int i = 0; i < 4; i++) acc[nc][i] = 0.f;

    #pragma unroll
    for (int kc = 0; kc < 4; kc++) {
        unsigned a0, a1, a2, a3;
        {
            unsigned addr = smem_u32(
                &sA[(warp * 16 + (lane & 15)) * APAD + kc * 16 + (lane >> 4) * 8]);
            asm volatile("ldmatrix.sync.aligned.m8n8.x4.shared.b16 {%0,%1,%2,%3}, [%4];"
                         : "=r"(a0), "=r"(a1), "=r"(a2), "=r"(a3) : "r"(addr));
        }
        #pragma unroll
        for (int nc = 0; nc < 8; nc++) {
            unsigned b0, b1;
            unsigned addr = smem_u32(&sB[(kc * 16 + (lane & 15)) * APAD + nc * 8]);
            asm volatile("ldmatrix.sync.aligned.m8n8.x2.trans.shared.b16 {%0,%1}, [%2];"
                         : "=r"(b0), "=r"(b1) : "r"(addr));
            asm volatile(
                "mma.sync.aligned.m16n8k16.row.col.f32.f16.f16.f32 "
                "{%0,%1,%2,%3}, {%4,%5,%6,%7}, {%8,%9}, {%0,%1,%2,%3};"
                : "+f"(acc[nc][0]), "+f"(acc[nc][1]), "+f"(acc[nc][2]), "+f"(acc[nc][3])
                : "r"(a0), "r"(a1), "r"(a2), "r"(a3), "r"(b0), "r"(b1));
        }
    }

    // Epilogue: rows r0 = warp*16 + lane/4 and r0+8; cols 2*(lane%4)+nc*8.
    int r0 = warp * 16 + (lane >> 2);
    int c0 = lane & 3;                  // half2 sub-index within n-chunk
    int node_a = node0 + r0;
    int node_b = node0 + r0 + 8;
    float dva = (node_a < N_NODES) ? g_dinv[node_a] : 0.f;
    float dvb = (node_b < N_NODES) ? g_dinv[node_b] : 0.f;
    __half2* T2 = (__half2*)g_t16;      // 32 half2 per row

    #pragma unroll
    for (int nc = 0; nc < 8; nc++) {
        int h2i = nc * 4 + c0;
        if (node_a < N_NODES)
            T2[node_a * 32 + h2i] = __floats2half2_rn(acc[nc][0] * dva, acc[nc][1] * dva);
        if (node_b < N_NODES)
            T2[node_b * 32 + h2i] = __floats2half2_rn(acc[nc][2] * dvb, acc[nc][3] * dvb);
    }
}

// ---------------------------------------------------------------------------
// Aggregate (pull-mode, fp16 gather, fp32 accumulate) + fused BN/ReLU
// (+ final linear head when last).  8 threads per node, 8 feats each (16B).
// ---------------------------------------------------------------------------
__global__ __launch_bounds__(256) void aggregate_kernel(
        const float* __restrict__ b,
        const float* __restrict__ gamma,
        const float* __restrict__ beta,
        const float* __restrict__ mean,
        const float* __restrict__ var,
        const float* __restrict__ lin_w,
        const float* __restrict__ lin_b,
        float* __restrict__ out,
        int last) {
    int t = blockIdx.x * blockDim.x + threadIdx.x;
    int node = t >> 3;
    int sub = t & 7;        // 8-feat group
    if (node >= N_NODES) return;

    const uint4* T = (const uint4*)g_t16;   // row = 8 uint4

    int s = g_off[node];
    int e = g_off[node + 1];

    float2 a0, a1, a2, a3;
    {
        uint4 v = T[node * 8 + sub];
        a0 = h2_to_f2(v.x); a1 = h2_to_f2(v.y);
        a2 = h2_to_f2(v.z); a3 = h2_to_f2(v.w);
    }

    int j = s;
    for (; j + 4 <= e; j += 4) {
        int n0 = __ldg(&g_csr[j + 0]);
        int n1 = __ldg(&g_csr[j + 1]);
        int n2 = __ldg(&g_csr[j + 2]);
        int n3 = __ldg(&g_csr[j + 3]);
        uint4 v0 = T[n0 * 8 + sub];
        uint4 v1 = T[n1 * 8 + sub];
        uint4 v2 = T[n2 * 8 + sub];
        uint4 v3 = T[n3 * 8 + sub];
        float2 f;
        f = h2_to_f2(v0.x); a0.x += f.x; a0.y += f.y;
        f = h2_to_f2(v0.y); a1.x += f.x; a1.y += f.y;
        f = h2_to_f2(v0.z); a2.x += f.x; a2.y += f.y;
        f = h2_to_f2(v0.w); a3.x += f.x; a3.y += f.y;
        f = h2_to_f2(v1.x); a0.x += f.x; a0.y += f.y;
        f = h2_to_f2(v1.y); a1.x += f.x; a1.y += f.y;
        f = h2_to_f2(v1.z); a2.x += f.x; a2.y += f.y;
        f = h2_to_f2(v1.w); a3.x += f.x; a3.y += f.y;
        f = h2_to_f2(v2.x); a0.x += f.x; a0.y += f.y;
        f = h2_to_f2(v2.y); a1.x += f.x; a1.y += f.y;
        f = h2_to_f2(v2.z); a2.x += f.x; a2.y += f.y;
        f = h2_to_f2(v2.w); a3.x += f.x; a3.y += f.y;
        f = h2_to_f2(v3.x); a0.x += f.x; a0.y += f.y;
        f = h2_to_f2(v3.y); a1.x += f.x; a1.y += f.y;
        f = h2_to_f2(v3.z); a2.x += f.x; a2.y += f.y;
        f = h2_to_f2(v3.w); a3.x += f.x; a3.y += f.y;
    }
    for (; j < e; j++) {
        int n = __ldg(&g_csr[j]);
        uint4 v = T[n * 8 + sub];
        float2 f;
        f = h2_to_f2(v.x); a0.x += f.x; a0.y += f.y;
        f = h2_to_f2(v.y); a1.x += f.x; a1.y += f.y;
        f = h2_to_f2(v.z); a2.x += f.x; a2.y += f.y;
        f = h2_to_f2(v.w); a3.x += f.x; a3.y += f.y;
    }

    float dv = g_dinv[node];
    float4 acc0 = make_float4(a0.x, a0.y, a1.x, a1.y);
    float4 acc1 = make_float4(a2.x, a2.y, a3.x, a3.y);

    float4 h0, h1;
    {
        float4 bb = ((const float4*)b)[sub * 2 + 0];
        float4 gm = ((const float4*)gamma)[sub * 2 + 0];
        float4 bt = ((const float4*)beta)[sub * 2 + 0];
        float4 mn = ((const float4*)mean)[sub * 2 + 0];
        float4 vr = ((const float4*)var)[sub * 2 + 0];
        h0.x = fmaxf(0.f, (acc0.x * dv + bb.x - mn.x) * rsqrtf(vr.x + BN_EPS) * gm.x + bt.x);
        h0.y = fmaxf(0.f, (acc0.y * dv + bb.y - mn.y) * rsqrtf(vr.y + BN_EPS) * gm.y + bt.y);
        h0.z = fmaxf(0.f, (acc0.z * dv + bb.z - mn.z) * rsqrtf(vr.z + BN_EPS) * gm.z + bt.z);
        h0.w = fmaxf(0.f, (acc0.w * dv + bb.w - mn.w) * rsqrtf(vr.w + BN_EPS) * gm.w + bt.w);
    }
    {
        float4 bb = ((const float4*)b)[sub * 2 + 1];
        float4 gm = ((const float4*)gamma)[sub * 2 + 1];
        float4 bt = ((const float4*)beta)[sub * 2 + 1];
        float4 mn = ((const float4*)mean)[sub * 2 + 1];
        float4 vr = ((const float4*)var)[sub * 2 + 1];
        h1.x = fmaxf(0.f, (acc1.x * dv + bb.x - mn.x) * rsqrtf(vr.x + BN_EPS) * gm.x + bt.x);
        h1.y = fmaxf(0.f, (acc1.y * dv + bb.y - mn.y) * rsqrtf(vr.y + BN_EPS) * gm.y + bt.y);
        h1.z = fmaxf(0.f, (acc1.z * dv + bb.z - mn.z) * rsqrtf(vr.z + BN_EPS) * gm.z + bt.z);
        h1.w = fmaxf(0.f, (acc1.w * dv + bb.w - mn.w) * rsqrtf(vr.w + BN_EPS) * gm.w + bt.w);
    }

    if (!last) {
        ((float4*)g_h)[node * 16 + sub * 2 + 0] = h0;
        ((float4*)g_h)[node * 16 + sub * 2 + 1] = h1;
    } else {
        float4 w0 = ((const float4*)lin_w)[sub * 2 + 0];
        float4 w1 = ((const float4*)lin_w)[sub * 2 + 1];
        float dot = h0.x * w0.x + h0.y * w0.y + h0.z * w0.z + h0.w * w0.w
                  + h1.x * w1.x + h1.y * w1.y + h1.z * w1.z + h1.w * w1.w;
        #pragma unroll
        for (int o = 4; o; o >>= 1)
            dot += __shfl_down_sync(0xFFFFFFFFu, dot, o, 8);
        if (sub == 0) out[node] = dot + lin_b[0];
    }
}

// ---------------------------------------------------------------------------
extern "C" void kernel_launch(void* const* d_in, const int* in_sizes, int n_in,
                              void* d_out, int out_size) {
    const float* x        = (const float*)d_in[0];
    const int*   ei       = (const int*)  d_in[1];   // [2, E]
    const float* Ws       = (const float*)d_in[2];   // [3, 64, 64]
    const float* bs       = (const float*)d_in[3];
    const float* gammas   = (const float*)d_in[4];
    const float* betas    = (const float*)d_in[5];
    const float* means    = (const float*)d_in[6];
    const float* variances= (const float*)d_in[7];
    const float* lin_w    = (const float*)d_in[8];
    const float* lin_b    = (const float*)d_in[9];

    const int* rowi = ei;
    const int* coli = ei + N_EDGES;

    const int e4_blocks = (N_EDGES / 4 + 255) / 256;
    hist_kernel<<<e4_blocks, 256>>>(coli);
    scan1_kernel<<<NB1, 256>>>();
    scan3_kernel<<<(N_NODES + 255) / 256, 256>>>();
    fill_kernel<<<e4_blocks, 256>>>(rowi, coli);

    const int gemm_blocks = (N_NODES + 127) / 128;
    const int agg_blocks = (N_NODES * 8 + 255) / 256;

    for (int l = 0; l < 3; l++) {
        const float* in = (l == 0) ? x : nullptr;   // nullptr -> g_h
        gemm_kernel<<<gemm_blocks, 256>>>(in, Ws + l * D * D);
        aggregate_kernel<<<agg_blocks, 256>>>(bs + l * D, gammas + l * D,
                                              betas + l * D, means + l * D,
                                              variances + l * D,
                                              lin_w, lin_b, (float*)d_out,
                                              (l == 2) ? 1 : 0);
    }
}

// round 8
// speedup vs baseline: 1.6061x; 1.0075x over previous
#include <cuda_runtime.h>
#include <cuda_fp16.h>
#include <cuda_bf16.h>

#define N_NODES 50000
#define N_EDGES 800000
#define D 64
#define BN_EPS 1e-5f

#define SCAN_BS 1024
#define NB1 ((N_NODES + SCAN_BS - 1) / SCAN_BS)   // 49

#define HIST_BLOCKS 782    // ceil(200000/256)
#define GEMM_TILES 391     // ceil(50000/128)
#define FILL_BLOCKS 782
#define SCALE_BLOCKS 1563  // ceil(400000/256)

// Scratch (device globals; no allocations allowed).
// INVARIANT: g_cnt is all-zero at kernel_launch entry (zero-init at load;
// scan1_kernel re-zeroes it after use within every call).
__device__ uint2  g_t16[N_NODES * 16];     // t' fp16 (row = 64 halves)
__device__ float4 g_h[N_NODES * (D/4)];    // layer output (fp32)
__device__ float  g_dinv[N_NODES];
__device__ int    g_cnt[N_NODES];
__device__ int    g_off[N_NODES + 1];
__device__ int    g_fill[N_NODES];
__device__ int    g_blk[NB1];
__device__ unsigned short g_csr[N_EDGES];  // source node per CSR slot (fits u16)

__device__ __forceinline__ float2 h2_to_f2(unsigned u) {
    __half2 h = *reinterpret_cast<__half2*>(&u);
    return __half22float2(h);
}
__device__ __forceinline__ unsigned f2_to_h2(float a, float b) {
    __half2 h = __floats2half2_rn(a, b);
    return *reinterpret_cast<unsigned*>(&h);
}
__device__ __forceinline__ unsigned smem_u32(const void* p) {
    return (unsigned)__cvta_generic_to_shared(p);
}

// ---------------------------------------------------------------------------
// GEMM tile body (HMMA): u = in @ W [* dinv], fp16 out to g_t16.
// 128-node tile, 256 threads; warp = 16 rows x 64 cols, mma.m16n8k16.
// ---------------------------------------------------------------------------
#define APAD 72

__device__ __forceinline__ void gemm_tile(int bid, const float* in,
                                          const float* W, bool scale) {
    __shared__ __half sA[128 * APAD];
    __shared__ __half sB[64 * APAD];

    int tid = threadIdx.x;
    int node0 = bid * 128;

    #pragma unroll
    for (int i = 0; i < 8; i++) {
        int g = tid + 256 * i;
        int k = g >> 5;
        int n2 = g & 31;
        float2 w = ((const float2*)W)[k * 32 + n2];
        *(__half2*)&sB[k * APAD + n2 * 2] = __floats2half2_rn(w.x, w.y);
    }
    #pragma unroll
    for (int i = 0; i < 8; i++) {
        int g = tid + 256 * i;
        int r = g >> 4;
        int c4 = g & 15;
        int node = node0 + r;
        float4 v = make_float4(0.f, 0.f, 0.f, 0.f);
        if (node < N_NODES) {
            if (in) v = ((const float4*)in)[node * 16 + c4];
            else    v = ((const float4*)g_h)[node * 16 + c4];
        }
        __half2* dst = (__half2*)&sA[r * APAD + c4 * 4];
        dst[0] = __floats2half2_rn(v.x, v.y);
        dst[1] = __floats2half2_rn(v.z, v.w);
    }
    __syncthreads();

    int warp = tid >> 5;
    int lane = tid & 31;

    float acc[8][4];
    #pragma unroll
    for (int nc = 0; nc < 8; nc++)
        #pragma unroll
        for (int i = 0; i < 4; i++) acc[nc][i] = 0.f;

    #pragma unroll
    for (int kc = 0; kc < 4; kc++) {
        unsigned a0, a1, a2, a3;
        {
            unsigned addr = smem_u32(
                &sA[(warp * 16 + (lane & 15)) * APAD + kc * 16 + (lane >> 4) * 8]);
            asm volatile("ldmatrix.sync.aligned.m8n8.x4.shared.b16 {%0,%1,%2,%3}, [%4];"
                         : "=r"(a0), "=r"(a1), "=r"(a2), "=r"(a3) : "r"(addr));
        }
        #pragma unroll
        for (int nc = 0; nc < 8; nc++) {
            unsigned b0, b1;
            unsigned addr = smem_u32(&sB[(kc * 16 + (lane & 15)) * APAD + nc * 8]);
            asm volatile("ldmatrix.sync.aligned.m8n8.x2.trans.shared.b16 {%0,%1}, [%2];"
                         : "=r"(b0), "=r"(b1) : "r"(addr));
            asm volatile(
                "mma.sync.aligned.m16n8k16.row.col.f32.f16.f16.f32 "
                "{%0,%1,%2,%3}, {%4,%5,%6,%7}, {%8,%9}, {%0,%1,%2,%3};"
                : "+f"(acc[nc][0]), "+f"(acc[nc][1]), "+f"(acc[nc][2]), "+f"(acc[nc][3])
                : "r"(a0), "r"(a1), "r"(a2), "r"(a3), "r"(b0), "r"(b1));
        }
    }

    int r0 = warp * 16 + (lane >> 2);
    int c0 = lane & 3;
    int node_a = node0 + r0;
    int node_b = node0 + r0 + 8;
    float dva = 1.f, dvb = 1.f;
    if (scale) {
        dva = (node_a < N_NODES) ? g_dinv[node_a] : 0.f;
        dvb = (node_b < N_NODES) ? g_dinv[node_b] : 0.f;
    }
    __half2* T2 = (__half2*)g_t16;

    #pragma unroll
    for (int nc = 0; nc < 8; nc++) {
        int h2i = nc * 4 + c0;
        if (node_a < N_NODES)
            T2[node_a * 32 + h2i] = __floats2half2_rn(acc[nc][0] * dva, acc[nc][1] * dva);
        if (node_b < N_NODES)
            T2[node_b * 32 + h2i] = __floats2half2_rn(acc[nc][2] * dvb, acc[nc][3] * dvb);
    }
}

// ---------------------------------------------------------------------------
// K1 (fat): hist (blocks [0, HIST_BLOCKS)) + unscaled layer-0 GEMM.
// ---------------------------------------------------------------------------
__global__ __launch_bounds__(256) void k1_hist_gemm0(const int* __restrict__ coli,
                                                     const float* __restrict__ x,
                                                     const float* __restrict__ W0) {
    if (blockIdx.x < HIST_BLOCKS) {
        int idx = blockIdx.x * 256 + threadIdx.x;
        if (idx < N_EDGES / 4) {
            int4 c = ((const int4*)coli)[idx];
            atomicAdd(&g_cnt[c.x], 1);
            atomicAdd(&g_cnt[c.y], 1);
            atomicAdd(&g_cnt[c.z], 1);
            atomicAdd(&g_cnt[c.w], 1);
        }
    } else {
        gemm_tile(blockIdx.x - HIST_BLOCKS, x, W0, false);
    }
}

// ---------------------------------------------------------------------------
// scan1: block partials + local offsets; also dinv and cnt re-zero.
// ---------------------------------------------------------------------------
__global__ __launch_bounds__(256) void scan1_kernel() {
    __shared__ int sh[8];
    int tid = threadIdx.x;
    int lane = tid & 31;
    int wid = tid >> 5;
    int base = blockIdx.x * SCAN_BS + tid * 4;

    int c[4];
    #pragma unroll
    for (int i = 0; i < 4; i++)
        c[i] = (base + i < N_NODES) ? g_cnt[base + i] : 0;
    int tot = c[0] + c[1] + c[2] + c[3];

    int v = tot;
    #pragma unroll
    for (int o = 1; o < 32; o <<= 1) {
        int n = __shfl_up_sync(0xFFFFFFFFu, v, o);
        if (lane >= o) v += n;
    }
    if (lane == 31) sh[wid] = v;
    __syncthreads();
    if (tid < 8) {
        int w = sh[tid];
        #pragma unroll
        for (int o = 1; o < 8; o <<= 1) {
            int n = __shfl_up_sync(0xFFu, w, o, 8);
            if (tid >= o) w += n;
        }
        sh[tid] = w;
    }
    __syncthreads();
    int incl = v + ((wid > 0) ? sh[wid - 1] : 0);
    int run = incl - tot;
    if (tid == 255) g_blk[blockIdx.x] = incl;
    #pragma unroll
    for (int i = 0; i < 4; i++) {
        if (base + i < N_NODES) {
            g_off[base + i] = run;
            g_dinv[base + i] = rsqrtf((float)(c[i] + 1));   // +1 self loop
            g_cnt[base + i] = 0;                            // restore invariant
        }
        run += c[i];
    }
}

// scan3: add cross-block prefix; set fill cursors.
__global__ __launch_bounds__(256) void scan3_kernel() {
    __shared__ int pref;
    int tid = threadIdx.x;
    if (tid == 0) pref = 0;
    __syncthreads();
    int chunk = (blockIdx.x * 256) >> 10;
    if (tid < chunk) atomicAdd(&pref, g_blk[tid]);   // chunk <= 48 < 256
    __syncthreads();

    int i = blockIdx.x * 256 + tid;
    if (i < N_NODES) {
        int off = g_off[i] + pref;
        g_off[i] = off;
        g_fill[i] = off;
        if (i == 0) g_off[N_NODES] = N_EDGES;
    }
}

// ---------------------------------------------------------------------------
// K4 (fat): fill (blocks [0, FILL_BLOCKS)) + dinv-scale of g_t16 (layer 0).
// ---------------------------------------------------------------------------
__global__ __launch_bounds__(256) void k4_fill_scale(const int* __restrict__ rowi,
                                                     const int* __restrict__ coli) {
    if (blockIdx.x < FILL_BLOCKS) {
        int idx = blockIdx.x * 256 + threadIdx.x;
        if (idx < N_EDGES / 4) {
            int4 r = ((const int4*)rowi)[idx];
            int4 c = ((const int4*)coli)[idx];
            int p0 = atomicAdd(&g_fill[c.x], 1);
            int p1 = atomicAdd(&g_fill[c.y], 1);
            int p2 = atomicAdd(&g_fill[c.z], 1);
            int p3 = atomicAdd(&g_fill[c.w], 1);
            g_csr[p0] = (unsigned short)r.x;
            g_csr[p1] = (unsigned short)r.y;
            g_csr[p2] = (unsigned short)r.z;
            g_csr[p3] = (unsigned short)r.w;
        }
    } else {
        int idx = (blockIdx.x - FILL_BLOCKS) * 256 + threadIdx.x;
        if (idx < N_NODES * 8) {
            int node = idx >> 3;
            float dv = g_dinv[node];
            uint4* p = ((uint4*)g_t16) + idx;
            uint4 v = *p;
            float2 f;
            f = h2_to_f2(v.x); v.x = f2_to_h2(f.x * dv, f.y * dv);
            f = h2_to_f2(v.y); v.y = f2_to_h2(f.x * dv, f.y * dv);
            f = h2_to_f2(v.z); v.z = f2_to_h2(f.x * dv, f.y * dv);
            f = h2_to_f2(v.w); v.w = f2_to_h2(f.x * dv, f.y * dv);
            *p = v;
        }
    }
}

// ---------------------------------------------------------------------------
// Standalone GEMM (layers 1,2): scaled.
// ---------------------------------------------------------------------------
__global__ __launch_bounds__(256) void gemm_kernel(const float* __restrict__ W) {
    gemm_tile(blockIdx.x, nullptr, W, true);
}

// ---------------------------------------------------------------------------
// Aggregate (pull-mode, fp16 gather, fp32 accumulate) + fused BN/ReLU
// (+ final linear head when last).  8 threads per node, 8 feats each (16B).
// ---------------------------------------------------------------------------
__global__ __launch_bounds__(256) void aggregate_kernel(
        const float* __restrict__ b,
        const float* __restrict__ gamma,
        const float* __restrict__ beta,
        const float* __restrict__ mean,
        const float* __restrict__ var,
        const float* __restrict__ lin_w,
        const float* __restrict__ lin_b,
        float* __restrict__ out,
        int last) {
    int t = blockIdx.x * blockDim.x + threadIdx.x;
    int node = t >> 3;
    int sub = t & 7;
    if (node >= N_NODES) return;

    const uint4* T = (const uint4*)g_t16;

    int s = g_off[node];
    int e = g_off[node + 1];

    float2 a0, a1, a2, a3;
    {
        uint4 v = T[node * 8 + sub];
        a0 = h2_to_f2(v.x); a1 = h2_to_f2(v.y);
        a2 = h2_to_f2(v.z); a3 = h2_to_f2(v.w);
    }

    int j = s;
    for (; j + 4 <= e; j += 4) {
        int n0 = g_csr[j + 0];
        int n1 = g_csr[j + 1];
        int n2 = g_csr[j + 2];
        int n3 = g_csr[j + 3];
        uint4 v0 = T[n0 * 8 + sub];
        uint4 v1 = T[n1 * 8 + sub];
        uint4 v2 = T[n2 * 8 + sub];
        uint4 v3 = T[n3 * 8 + sub];
        float2 f;
        f = h2_to_f2(v0.x); a0.x += f.x; a0.y += f.y;
        f = h2_to_f2(v0.y); a1.x += f.x; a1.y += f.y;
        f = h2_to_f2(v0.z); a2.x += f.x; a2.y += f.y;
        f = h2_to_f2(v0.w); a3.x += f.x; a3.y += f.y;
        f = h2_to_f2(v1.x); a0.x += f.x; a0.y += f.y;
        f = h2_to_f2(v1.y); a1.x += f.x; a1.y += f.y;
        f = h2_to_f2(v1.z); a2.x += f.x; a2.y += f.y;
        f = h2_to_f2(v1.w); a3.x += f.x; a3.y += f.y;
        f = h2_to_f2(v2.x); a0.x += f.x; a0.y += f.y;
        f = h2_to_f2(v2.y); a1.x += f.x; a1.y += f.y;
        f = h2_to_f2(v2.z); a2.x += f.x; a2.y += f.y;
        f = h2_to_f2(v2.w); a3.x += f.x; a3.y += f.y;
        f = h2_to_f2(v3.x); a0.x += f.x; a0.y += f.y;
        f = h2_to_f2(v3.y); a1.x += f.x; a1.y += f.y;
        f = h2_to_f2(v3.z); a2.x += f.x; a2.y += f.y;
        f = h2_to_f2(v3.w); a3.x += f.x; a3.y += f.y;
    }
    for (; j < e; j++) {
        int n = g_csr[j];
        uint4 v = T[n * 8 + sub];
        float2 f;
        f = h2_to_f2(v.x); a0.x += f.x; a0.y += f.y;
        f = h2_to_f2(v.y); a1.x += f.x; a1.y += f.y;
        f = h2_to_f2(v.z); a2.x += f.x; a2.y += f.y;
        f = h2_to_f2(v.w); a3.x += f.x; a3.y += f.y;
    }

    float dv = g_dinv[node];
    float4 acc0 = make_float4(a0.x, a0.y, a1.x, a1.y);
    float4 acc1 = make_float4(a2.x, a2.y, a3.x, a3.y);

    float4 h0, h1;
    {
        float4 bb = ((const float4*)b)[sub * 2 + 0];
        float4 gm = ((const float4*)gamma)[sub * 2 + 0];
        float4 bt = ((const float4*)beta)[sub * 2 + 0];
        float4 mn = ((const float4*)mean)[sub * 2 + 0];
        float4 vr = ((const float4*)var)[sub * 2 + 0];
        h0.x = fmaxf(0.f, (acc0.x * dv + bb.x - mn.x) * rsqrtf(vr.x + BN_EPS) * gm.x + bt.x);
        h0.y = fmaxf(0.f, (acc0.y * dv + bb.y - mn.y) * rsqrtf(vr.y + BN_EPS) * gm.y + bt.y);
        h0.z = fmaxf(0.f, (acc0.z * dv + bb.z - mn.z) * rsqrtf(vr.z + BN_EPS) * gm.z + bt.z);
        h0.w = fmaxf(0.f, (acc0.w * dv + bb.w - mn.w) * rsqrtf(vr.w + BN_EPS) * gm.w + bt.w);
    }
    {
        float4 bb = ((const float4*)b)[sub * 2 + 1];
        float4 gm = ((const float4*)gamma)[sub * 2 + 1];
        float4 bt = ((const float4*)beta)[sub * 2 + 1];
        float4 mn = ((const float4*)mean)[sub * 2 + 1];
        float4 vr = ((const float4*)var)[sub * 2 + 1];
        h1.x = fmaxf(0.f, (acc1.x * dv + bb.x - mn.x) * rsqrtf(vr.x + BN_EPS) * gm.x + bt.x);
        h1.y = fmaxf(0.f, (acc1.y * dv + bb.y - mn.y) * rsqrtf(vr.y + BN_EPS) * gm.y + bt.y);
        h1.z = fmaxf(0.f, (acc1.z * dv + bb.z - mn.z) * rsqrtf(vr.z + BN_EPS) * gm.z + bt.z);
        h1.w = fmaxf(0.f, (acc1.w * dv + bb.w - mn.w) * rsqrtf(vr.w + BN_EPS) * gm.w + bt.w);
    }

    if (!last) {
        ((float4*)g_h)[node * 16 + sub * 2 + 0] = h0;
        ((float4*)g_h)[node * 16 + sub * 2 + 1] = h1;
    } else {
        float4 w0 = ((const float4*)lin_w)[sub * 2 + 0];
        float4 w1 = ((const float4*)lin_w)[sub * 2 + 1];
        float dot = h0.x * w0.x + h0.y * w0.y + h0.z * w0.z + h0.w * w0.w
                  + h1.x * w1.x + h1.y * w1.y + h1.z * w1.z + h1.w * w1.w;
        #pragma unroll
        for (int o = 4; o; o >>= 1)
            dot += __shfl_down_sync(0xFFFFFFFFu, dot, o, 8);
        if (sub == 0) out[node] = dot + lin_b[0];
    }
}

// ---------------------------------------------------------------------------
extern "C" void kernel_launch(void* const* d_in, const int* in_sizes, int n_in,
                              void* d_out, int out_size) {
    const float* x        = (const float*)d_in[0];
    const int*   ei       = (const int*)  d_in[1];   // [2, E]
    const float* Ws       = (const float*)d_in[2];   // [3, 64, 64]
    const float* bs       = (const float*)d_in[3];
    const float* gammas   = (const float*)d_in[4];
    const float* betas    = (const float*)d_in[5];
    const float* means    = (const float*)d_in[6];
    const float* variances= (const float*)d_in[7];
    const float* lin_w    = (const float*)d_in[8];
    const float* lin_b    = (const float*)d_in[9];

    const int* rowi = ei;
    const int* coli = ei + N_EDGES;

    const int agg_blocks = (N_NODES * 8 + 255) / 256;

    // K1: hist + unscaled layer-0 GEMM (independent, overlapped)
    k1_hist_gemm0<<<HIST_BLOCKS + GEMM_TILES, 256>>>(coli, x, Ws);
    scan1_kernel<<<NB1, 256>>>();
    scan3_kernel<<<(N_NODES + 255) / 256, 256>>>();
    // K4: CSR fill + dinv-scale of layer-0 t' (independent, overlapped)
    k4_fill_scale<<<FILL_BLOCKS + SCALE_BLOCKS, 256>>>(rowi, coli);

    for (int l = 0; l < 3; l++) {
        if (l > 0)
            gemm_kernel<<<GEMM_TILES, 256>>>(Ws + l * D * D);
        aggregate_kernel<<<agg_blocks, 256>>>(bs + l * D, gammas + l * D,
                                              betas + l * D, means + l * D,
                                              variances + l * D,
                                              lin_w, lin_b, (float*)d_out,
                                              (l == 2) ? 1 : 0);
    }
}